// round 1
// baseline (speedup 1.0000x reference)
#include <cuda_runtime.h>
#include <math.h>

#define NN 50000
#define EE 400000
#define DH 128
#define DE 32
#define NH 8
#define CH 16

typedef unsigned long long ull;

// ---------------- scratch (device globals: no allocation allowed) ----------------
__device__ float g_q[(size_t)NN * DH];
__device__ float g_k[(size_t)NN * DH];
__device__ float g_v[(size_t)NN * DH];
__device__ float g_agg[(size_t)NN * DH];
__device__ float g_feat[(size_t)NN * DH];
__device__ float g_raw[(size_t)EE * NH];
__device__ unsigned int g_maxenc[(size_t)NN * NH];
__device__ float g_sum[(size_t)NN * NH];

// ---------------- packed f32x2 helpers (2x fp32 FMA rate on sm_103a) -------------
__device__ __forceinline__ ull pk2(float lo, float hi) {
    ull r; asm("mov.b64 %0, {%1, %2};" : "=l"(r) : "f"(lo), "f"(hi)); return r;
}
__device__ __forceinline__ float2 upk2(ull a) {
    float2 r; asm("mov.b64 {%0, %1}, %2;" : "=f"(r.x), "=f"(r.y) : "l"(a)); return r;
}
__device__ __forceinline__ ull ffma2(ull a, ull b, ull c) {
    ull d; asm("fma.rn.f32x2 %0, %1, %2, %3;" : "=l"(d) : "l"(a), "l"(b), "l"(c)); return d;
}
__device__ __forceinline__ ull fadd2(ull a, ull b) {
    ull d; asm("add.rn.f32x2 %0, %1, %2;" : "=l"(d) : "l"(a), "l"(b)); return d;
}
__device__ __forceinline__ ull fmul2(ull a, ull b) {
    ull d; asm("mul.rn.f32x2 %0, %1, %2;" : "=l"(d) : "l"(a), "l"(b)); return d;
}
__device__ __forceinline__ void red_add_v4(float* p, float a, float b, float c, float d) {
    asm volatile("red.global.add.v4.f32 [%0], {%1, %2, %3, %4};"
                 :: "l"(p), "f"(a), "f"(b), "f"(c), "f"(d) : "memory");
}

// monotonic float<->uint encoding for atomicMax over signed floats
__device__ __forceinline__ unsigned fenc(float f) {
    unsigned u = __float_as_uint(f);
    return (u & 0x80000000u) ? ~u : (u | 0x80000000u);
}
__device__ __forceinline__ float fdec(unsigned u) {
    return __uint_as_float((u & 0x80000000u) ? (u ^ 0x80000000u) : ~u);
}

// ---------------- fused 4-way node projection GEMM -------------------------------
// out = h @ W^T + b for W in {Wq, Wk, Wv, Wskip}; [N,128] x [128,128]
#define BN 64
#define WPAD 132
#define PROJ_THREADS 256
#define PROJ_SMEM ((BN * DH + DH * WPAD) * 4)

__global__ void proj_kernel(const float* __restrict__ hin,
                            const float* __restrict__ Wq, const float* __restrict__ bq,
                            const float* __restrict__ Wk, const float* __restrict__ bk,
                            const float* __restrict__ Wv, const float* __restrict__ bv,
                            const float* __restrict__ Ws, const float* __restrict__ bs) {
    extern __shared__ float sh[];
    float* xs  = sh;             // [BN][DH]
    float* wsT = sh + BN * DH;   // [DH][WPAD]  (transposed weight, padded)
    const int tid = threadIdx.x;
    const int node0 = blockIdx.x * BN;

    // load node tile (zero-fill OOB rows)
    for (int i = tid; i < BN * DH / 4; i += PROJ_THREADS) {
        int n  = i / (DH / 4);
        int c4 = (i % (DH / 4)) * 4;
        float4 v = make_float4(0.f, 0.f, 0.f, 0.f);
        if (node0 + n < NN) v = *(const float4*)(hin + (size_t)(node0 + n) * DH + c4);
        *(float4*)(xs + n * DH + c4) = v;
    }

    const int cgrp = tid & 31;       // 32 channel groups of 4
    const int ngrp = tid >> 5;       // 8 node groups of 8
    const int c0 = cgrp * 4;

    const float* Wlist[4] = {Wq, Wk, Wv, Ws};
    const float* Blist[4] = {bq, bk, bv, bs};
    float* Olist[4] = {g_q, g_k, g_v, g_agg};

    for (int w = 0; w < 4; ++w) {
        __syncthreads();
        const float* W = Wlist[w];
        for (int t = tid; t < DH * DH; t += PROJ_THREADS) {
            int ch = t >> 7, kk = t & (DH - 1);
            wsT[kk * WPAD + ch] = W[t];         // transpose into smem
        }
        __syncthreads();

        ull acc0[8], acc1[8];
#pragma unroll
        for (int i = 0; i < 8; ++i) { acc0[i] = 0ULL; acc1[i] = 0ULL; }

        const float* xrow = xs + (ngrp * 8) * DH;
#pragma unroll 8
        for (int kk = 0; kk < DH; ++kk) {
            ulonglong2 wp = *(const ulonglong2*)(wsT + kk * WPAD + c0); // 4 ch as 2 pairs
#pragma unroll
            for (int i = 0; i < 8; ++i) {
                float xv = xrow[i * DH + kk];   // broadcast within warp
                ull xx = pk2(xv, xv);
                acc0[i] = ffma2(xx, wp.x, acc0[i]);
                acc1[i] = ffma2(xx, wp.y, acc1[i]);
            }
        }

        float4 bias = *(const float4*)(Blist[w] + c0);
        float* O = Olist[w];
#pragma unroll
        for (int i = 0; i < 8; ++i) {
            int n = node0 + ngrp * 8 + i;
            if (n < NN) {
                float2 a = upk2(acc0[i]), b = upk2(acc1[i]);
                float4 o = make_float4(a.x + bias.x, a.y + bias.y, b.x + bias.z, b.y + bias.w);
                *(float4*)(O + (size_t)n * DH + c0) = o;
            }
        }
    }
}

// ---------------- softmax state init ---------------------------------------------
__global__ void initms_kernel() {
    int i = blockIdx.x * blockDim.x + threadIdx.x;
    if (i < NN * NH) {
        g_maxenc[i] = 0x007FFFFFu;   // fenc(-inf)
        g_sum[i] = 0.f;
    }
}

// ---------------- edge kernels ----------------------------------------------------
#define EB 32   // edges per block, 8 threads (one per head) per edge => 256 threads

__device__ __forceinline__ void load_edge_smem(const float* __restrict__ We,
                                               const float* __restrict__ ef,
                                               const int* __restrict__ eidx, int e0,
                                               float (*WeT)[WPAD], float (*efs)[DE + 1],
                                               int* ssrc, int* sdst) {
    int tid = threadIdx.x;
    for (int t = tid; t < DH * DE; t += 256) {      // WeT[d][ch] = We[ch][d]
        int ch = t >> 5, d = t & 31;
        WeT[d][ch] = We[t];
    }
    for (int t = tid; t < EB * DE; t += 256) {
        int el = t >> 5, d = t & 31;
        efs[el][d] = ef[(size_t)e0 * DE + t];
    }
    if (tid < EB) {
        ssrc[tid] = eidx[e0 + tid];
        sdst[tid] = eidx[EE + e0 + tid];
    }
    __syncthreads();
}

// e-projection for (edge el, head hh): 16 channels as 8 f32x2 pairs
__device__ __forceinline__ void eproj(const float (*WeT)[WPAD], const float (*efs)[DE + 1],
                                      int el, int hh, ull ev[8]) {
#pragma unroll
    for (int j = 0; j < 8; ++j) ev[j] = 0ULL;
#pragma unroll
    for (int d = 0; d < DE; ++d) {
        float x = efs[el][d];
        ull xx = pk2(x, x);
        const ulonglong2* wr = (const ulonglong2*)(&WeT[d][hh * CH]);
        ulonglong2 w0 = wr[0], w1 = wr[1], w2 = wr[2], w3 = wr[3];
        ev[0] = ffma2(xx, w0.x, ev[0]); ev[1] = ffma2(xx, w0.y, ev[1]);
        ev[2] = ffma2(xx, w1.x, ev[2]); ev[3] = ffma2(xx, w1.y, ev[3]);
        ev[4] = ffma2(xx, w2.x, ev[4]); ev[5] = ffma2(xx, w2.y, ev[5]);
        ev[6] = ffma2(xx, w3.x, ev[6]); ev[7] = ffma2(xx, w3.y, ev[7]);
    }
}

// pass A: raw alpha + segment max
__global__ void edgeA_kernel(const float* __restrict__ We, const float* __restrict__ ef,
                             const int* __restrict__ eidx) {
    __shared__ float WeT[DE][WPAD];
    __shared__ float efs[EB][DE + 1];
    __shared__ int ssrc[EB], sdst[EB];
    int e0 = blockIdx.x * EB;
    load_edge_smem(We, ef, eidx, e0, WeT, efs, ssrc, sdst);

    int tid = threadIdx.x;
    int el = tid >> 3, hh = tid & 7;
    int e = e0 + el;
    if (e >= EE) return;
    int src = ssrc[el], dst = sdst[el];

    ull ev[8];
    eproj(WeT, efs, el, hh, ev);

    const ulonglong2* qp = (const ulonglong2*)(g_q + (size_t)dst * DH + hh * CH);
    const ulonglong2* kp = (const ulonglong2*)(g_k + (size_t)src * DH + hh * CH);
    ull acc = 0ULL;
#pragma unroll
    for (int j = 0; j < 4; ++j) {
        ulonglong2 q2 = qp[j], k2 = kp[j];
        acc = ffma2(q2.x, fadd2(k2.x, ev[2 * j]), acc);
        acc = ffma2(q2.y, fadd2(k2.y, ev[2 * j + 1]), acc);
    }
    float2 r = upk2(acc);
    float raw = (r.x + r.y) * 0.25f;   // / sqrt(C=16)
    g_raw[(size_t)e * NH + hh] = raw;
    atomicMax(&g_maxenc[(size_t)dst * NH + hh], fenc(raw));
}

// pass B: exp + segment sum
__global__ void edgeB_kernel(const int* __restrict__ eidx) {
    int i = blockIdx.x * blockDim.x + threadIdx.x;
    if (i >= EE * NH) return;
    int e = i >> 3, hh = i & 7;
    int dst = eidx[EE + e];
    float m = fdec(g_maxenc[(size_t)dst * NH + hh]);
    float v = expf(g_raw[i] - m);
    g_raw[i] = v;
    atomicAdd(&g_sum[(size_t)dst * NH + hh], v);
}

// pass C: normalize, emit alpha, scatter message with vectorized reductions
__global__ void edgeC_kernel(const float* __restrict__ We, const float* __restrict__ ef,
                             const int* __restrict__ eidx, float* __restrict__ alpha_out) {
    __shared__ float WeT[DE][WPAD];
    __shared__ float efs[EB][DE + 1];
    __shared__ int ssrc[EB], sdst[EB];
    int e0 = blockIdx.x * EB;
    load_edge_smem(We, ef, eidx, e0, WeT, efs, ssrc, sdst);

    int tid = threadIdx.x;
    int el = tid >> 3, hh = tid & 7;
    int e = e0 + el;
    if (e >= EE) return;
    int src = ssrc[el], dst = sdst[el];

    float expv = g_raw[(size_t)e * NH + hh];
    float s = g_sum[(size_t)dst * NH + hh];
    float a = expv / (s + 1e-16f);
    alpha_out[(size_t)e * NH + hh] = a;

    ull ev[8];
    eproj(WeT, efs, el, hh, ev);

    const ulonglong2* vp = (const ulonglong2*)(g_v + (size_t)src * DH + hh * CH);
    float* aggp = g_agg + (size_t)dst * DH + hh * CH;
    ull a2 = pk2(a, a);
#pragma unroll
    for (int j = 0; j < 4; ++j) {
        ulonglong2 v2 = vp[j];
        ull m0 = fmul2(fadd2(v2.x, ev[2 * j]), a2);
        ull m1 = fmul2(fadd2(v2.y, ev[2 * j + 1]), a2);
        float2 f0 = upk2(m0), f1 = upk2(m1);
        red_add_v4(aggp + j * 4, f0.x, f0.y, f1.x, f1.y);
    }
}

// ---------------- epilogue: exact-erf GELU + feature handoff ----------------------
__global__ void finish_kernel(float* __restrict__ dst, int apply_gelu) {
    int i = blockIdx.x * blockDim.x + threadIdx.x;
    if (i >= NN * DH) return;
    float x = g_agg[i];
    if (apply_gelu) x = x * normcdff(x);   // 0.5*x*(1+erf(x/sqrt(2)))
    dst[i] = x;
}

// ---------------- launch ----------------------------------------------------------
extern "C" void kernel_launch(void* const* d_in, const int* in_sizes, int n_in,
                              void* d_out, int out_size) {
    const float* x   = (const float*)d_in[0];
    const float* ef  = (const float*)d_in[1];
    const float* Wq  = (const float*)d_in[2];
    const float* bq  = (const float*)d_in[3];
    const float* Wk  = (const float*)d_in[4];
    const float* bk  = (const float*)d_in[5];
    const float* Wv  = (const float*)d_in[6];
    const float* bv  = (const float*)d_in[7];
    const float* We  = (const float*)d_in[8];
    const float* Ws  = (const float*)d_in[9];
    const float* bs  = (const float*)d_in[10];
    const int* eidx  = (const int*)d_in[11];
    float* out = (float*)d_out;

    cudaFuncSetAttribute(proj_kernel, cudaFuncAttributeMaxDynamicSharedMemorySize, PROJ_SMEM);
    float* feat = nullptr;
    cudaGetSymbolAddress((void**)&feat, g_feat);

    const int nproj = (NN + BN - 1) / BN;
    const int nedge = EE / EB;

    for (int l = 0; l < 4; ++l) {
        const float* hin = (l == 0) ? x : feat;
        size_t off2 = (size_t)l * DH * DH;
        size_t offb = (size_t)l * DH;
        size_t offe = (size_t)l * DH * DE;

        initms_kernel<<<(NN * NH + 255) / 256, 256>>>();
        proj_kernel<<<nproj, PROJ_THREADS, PROJ_SMEM>>>(hin,
            Wq + off2, bq + offb, Wk + off2, bk + offb,
            Wv + off2, bv + offb, Ws + off2, bs + offb);
        edgeA_kernel<<<nedge, 256>>>(We + offe, ef, eidx);
        edgeB_kernel<<<(EE * NH + 255) / 256, 256>>>(eidx);
        edgeC_kernel<<<nedge, 256>>>(We + offe, ef, eidx,
            out + (size_t)NN * DH + (size_t)l * EE * NH);
        finish_kernel<<<(NN * DH + 255) / 256, 256>>>((l == 3) ? out : feat, (l < 3) ? 1 : 0);
    }
}

// round 5
// speedup vs baseline: 1.9632x; 1.9632x over previous
#include <cuda_runtime.h>
#include <math.h>

#define NN 50000
#define EE 400000
#define DH 128
#define DE 32
#define NH 8
#define CH 16

typedef unsigned long long ull;

// ---------------- scratch (device globals: no allocation allowed) ----------------
__device__ float g_q[(size_t)NN * DH];
__device__ float g_k[(size_t)NN * DH];
__device__ float g_v[(size_t)NN * DH];
__device__ float g_agg[(size_t)NN * DH];
__device__ float g_feat[(size_t)NN * DH];
__device__ float g_e[(size_t)EE * DH];          // materialized edge projection
__device__ float g_raw[(size_t)EE * NH];
__device__ unsigned int g_maxenc[(size_t)NN * NH];
__device__ float g_sum[(size_t)NN * NH];

// ---------------- packed f32x2 helpers (2x fp32 FMA rate on sm_103a) -------------
__device__ __forceinline__ ull pk2(float lo, float hi) {
    ull r; asm("mov.b64 %0, {%1, %2};" : "=l"(r) : "f"(lo), "f"(hi)); return r;
}
__device__ __forceinline__ float2 upk2(ull a) {
    float2 r; asm("mov.b64 {%0, %1}, %2;" : "=f"(r.x), "=f"(r.y) : "l"(a)); return r;
}
__device__ __forceinline__ ull ffma2(ull a, ull b, ull c) {
    ull d; asm("fma.rn.f32x2 %0, %1, %2, %3;" : "=l"(d) : "l"(a), "l"(b), "l"(c)); return d;
}
__device__ __forceinline__ ull fadd2(ull a, ull b) {
    ull d; asm("add.rn.f32x2 %0, %1, %2;" : "=l"(d) : "l"(a), "l"(b)); return d;
}
__device__ __forceinline__ ull fmul2(ull a, ull b) {
    ull d; asm("mul.rn.f32x2 %0, %1, %2;" : "=l"(d) : "l"(a), "l"(b)); return d;
}
__device__ __forceinline__ void red_add_v4(float* p, float a, float b, float c, float d) {
    asm volatile("red.global.add.v4.f32 [%0], {%1, %2, %3, %4};"
                 :: "l"(p), "f"(a), "f"(b), "f"(c), "f"(d) : "memory");
}

// monotonic float<->uint encoding for atomicMax over signed floats
__device__ __forceinline__ unsigned fenc(float f) {
    unsigned u = __float_as_uint(f);
    return (u & 0x80000000u) ? ~u : (u | 0x80000000u);
}
__device__ __forceinline__ float fdec(unsigned u) {
    return __uint_as_float((u & 0x80000000u) ? (u ^ 0x80000000u) : ~u);
}

// ---------------- fused 4-way node projection GEMM (unchanged, known-good) -------
#define BN 64
#define WPAD 132
#define PROJ_THREADS 256
#define PROJ_SMEM ((BN * DH + DH * WPAD) * 4)

__global__ void proj_kernel(const float* __restrict__ hin,
                            const float* __restrict__ Wq, const float* __restrict__ bq,
                            const float* __restrict__ Wk, const float* __restrict__ bk,
                            const float* __restrict__ Wv, const float* __restrict__ bv,
                            const float* __restrict__ Ws, const float* __restrict__ bs) {
    extern __shared__ float sh[];
    float* xs  = sh;             // [BN][DH]
    float* wsT = sh + BN * DH;   // [DH][WPAD]
    const int tid = threadIdx.x;
    const int node0 = blockIdx.x * BN;

    for (int i = tid; i < BN * DH / 4; i += PROJ_THREADS) {
        int n  = i / (DH / 4);
        int c4 = (i % (DH / 4)) * 4;
        float4 v = make_float4(0.f, 0.f, 0.f, 0.f);
        if (node0 + n < NN) v = *(const float4*)(hin + (size_t)(node0 + n) * DH + c4);
        *(float4*)(xs + n * DH + c4) = v;
    }

    const int cgrp = tid & 31;
    const int ngrp = tid >> 5;
    const int c0 = cgrp * 4;

    const float* Wlist[4] = {Wq, Wk, Wv, Ws};
    const float* Blist[4] = {bq, bk, bv, bs};
    float* Olist[4] = {g_q, g_k, g_v, g_agg};

    for (int w = 0; w < 4; ++w) {
        __syncthreads();
        const float* W = Wlist[w];
        for (int t = tid; t < DH * DH; t += PROJ_THREADS) {
            int ch = t >> 7, kk = t & (DH - 1);
            wsT[kk * WPAD + ch] = W[t];
        }
        __syncthreads();

        ull acc0[8], acc1[8];
#pragma unroll
        for (int i = 0; i < 8; ++i) { acc0[i] = 0ULL; acc1[i] = 0ULL; }

        const float* xrow = xs + (ngrp * 8) * DH;
#pragma unroll 8
        for (int kk = 0; kk < DH; ++kk) {
            ulonglong2 wp = *(const ulonglong2*)(wsT + kk * WPAD + c0);
#pragma unroll
            for (int i = 0; i < 8; ++i) {
                float xv = xrow[i * DH + kk];
                ull xx = pk2(xv, xv);
                acc0[i] = ffma2(xx, wp.x, acc0[i]);
                acc1[i] = ffma2(xx, wp.y, acc1[i]);
            }
        }

        float4 bias = *(const float4*)(Blist[w] + c0);
        float* O = Olist[w];
#pragma unroll
        for (int i = 0; i < 8; ++i) {
            int n = node0 + ngrp * 8 + i;
            if (n < NN) {
                float2 a = upk2(acc0[i]), b = upk2(acc1[i]);
                float4 o = make_float4(a.x + bias.x, a.y + bias.y, b.x + bias.z, b.y + bias.w);
                *(float4*)(O + (size_t)n * DH + c0) = o;
            }
        }
    }
}

// ---------------- edge projection GEMM: g_e = ef @ We^T  [E,32]x[32,128] ----------
#define EPB 64   // edges per block
__global__ void eproj_kernel(const float* __restrict__ We, const float* __restrict__ ef) {
    __shared__ float ws[DE][WPAD];      // ws[k][ch] = We[ch][k]
    __shared__ float efs[EPB][DE + 1];
    const int tid = threadIdx.x;
    const int e0 = blockIdx.x * EPB;

    for (int t = tid; t < DH * DE; t += 256) {
        int ch = t >> 5, k = t & (DE - 1);
        ws[k][ch] = We[t];
    }
    for (int t = tid; t < EPB * DE; t += 256) {
        efs[t >> 5][t & (DE - 1)] = ef[(size_t)e0 * DE + t];
    }
    __syncthreads();

    const int egrp = tid >> 5;       // 8 groups of 8 edges
    const int cg = tid & 31;         // 32 channel groups of 4
    const int c0 = cg * 4;

    ull acc0[8], acc1[8];
#pragma unroll
    for (int i = 0; i < 8; ++i) { acc0[i] = 0ULL; acc1[i] = 0ULL; }

#pragma unroll
    for (int k = 0; k < DE; ++k) {
        ulonglong2 wp = *(const ulonglong2*)(&ws[k][c0]);   // 16B-stride: full-BW, no conflict
#pragma unroll
        for (int i = 0; i < 8; ++i) {
            float xv = efs[egrp * 8 + i][k];                // broadcast
            ull xx = pk2(xv, xv);
            acc0[i] = ffma2(xx, wp.x, acc0[i]);
            acc1[i] = ffma2(xx, wp.y, acc1[i]);
        }
    }

#pragma unroll
    for (int i = 0; i < 8; ++i) {
        int e = e0 + egrp * 8 + i;
        float2 a = upk2(acc0[i]), b = upk2(acc1[i]);
        *(float4*)(g_e + (size_t)e * DH + c0) = make_float4(a.x, a.y, b.x, b.y);
    }
}

// ---------------- softmax state init ---------------------------------------------
__global__ void initms_kernel() {
    int i = blockIdx.x * blockDim.x + threadIdx.x;
    if (i < NN * NH) {
        g_maxenc[i] = 0x007FFFFFu;   // fenc(-inf)
        g_sum[i] = 0.f;
    }
}

// ---------------- pass A: raw alpha + segment max (pure gather) -------------------
__global__ void edgeA_kernel(const int* __restrict__ eidx) {
    int gt = blockIdx.x * 256 + threadIdx.x;
    if (gt >= EE * NH) return;
    int e = gt >> 3, hh = gt & 7;
    int src = eidx[e], dst = eidx[EE + e];

    const ulonglong2* qp = (const ulonglong2*)(g_q + (size_t)dst * DH + hh * CH);
    const ulonglong2* kp = (const ulonglong2*)(g_k + (size_t)src * DH + hh * CH);
    const ulonglong2* ep = (const ulonglong2*)(g_e + (size_t)e   * DH + hh * CH);

    ull acc = 0ULL;
#pragma unroll
    for (int j = 0; j < 4; ++j) {
        ulonglong2 q2 = qp[j], k2 = kp[j], e2 = ep[j];
        acc = ffma2(q2.x, fadd2(k2.x, e2.x), acc);
        acc = ffma2(q2.y, fadd2(k2.y, e2.y), acc);
    }
    float2 r = upk2(acc);
    float raw = (r.x + r.y) * 0.25f;   // / sqrt(C=16)
    g_raw[gt] = raw;
    atomicMax(&g_maxenc[(size_t)dst * NH + hh], fenc(raw));
}

// ---------------- pass B: exp + segment sum ---------------------------------------
__global__ void edgeB_kernel(const int* __restrict__ eidx) {
    int i = blockIdx.x * blockDim.x + threadIdx.x;
    if (i >= EE * NH) return;
    int e = i >> 3, hh = i & 7;
    int dst = eidx[EE + e];
    float m = fdec(g_maxenc[(size_t)dst * NH + hh]);
    float v = expf(g_raw[i] - m);
    g_raw[i] = v;
    atomicAdd(&g_sum[(size_t)dst * NH + hh], v);
}

// ---------------- pass C: normalize, alpha out, message scatter -------------------
__global__ void edgeC_kernel(const int* __restrict__ eidx, float* __restrict__ alpha_out) {
    int gt = blockIdx.x * 256 + threadIdx.x;
    if (gt >= EE * NH) return;
    int e = gt >> 3, hh = gt & 7;
    int src = eidx[e], dst = eidx[EE + e];

    float expv = g_raw[gt];
    float s = g_sum[(size_t)dst * NH + hh];
    float a = expv / (s + 1e-16f);
    alpha_out[gt] = a;

    const ulonglong2* vp = (const ulonglong2*)(g_v + (size_t)src * DH + hh * CH);
    const ulonglong2* ep = (const ulonglong2*)(g_e + (size_t)e   * DH + hh * CH);
    float* aggp = g_agg + (size_t)dst * DH + hh * CH;
    ull a2 = pk2(a, a);
#pragma unroll
    for (int j = 0; j < 4; ++j) {
        ulonglong2 v2 = vp[j], e2 = ep[j];
        ull m0 = fmul2(fadd2(v2.x, e2.x), a2);
        ull m1 = fmul2(fadd2(v2.y, e2.y), a2);
        float2 f0 = upk2(m0), f1 = upk2(m1);
        red_add_v4(aggp + j * 4, f0.x, f0.y, f1.x, f1.y);
    }
}

// ---------------- epilogue: exact-erf GELU + feature handoff ----------------------
__global__ void finish_kernel(float* __restrict__ dst, int apply_gelu) {
    int i = blockIdx.x * blockDim.x + threadIdx.x;
    if (i >= NN * DH) return;
    float x = g_agg[i];
    if (apply_gelu) x = x * normcdff(x);   // 0.5*x*(1+erf(x/sqrt(2)))
    dst[i] = x;
}

// ---------------- launch ----------------------------------------------------------
extern "C" void kernel_launch(void* const* d_in, const int* in_sizes, int n_in,
                              void* d_out, int out_size) {
    const float* x   = (const float*)d_in[0];
    const float* ef  = (const float*)d_in[1];
    const float* Wq  = (const float*)d_in[2];
    const float* bq  = (const float*)d_in[3];
    const float* Wk  = (const float*)d_in[4];
    const float* bk  = (const float*)d_in[5];
    const float* Wv  = (const float*)d_in[6];
    const float* bv  = (const float*)d_in[7];
    const float* We  = (const float*)d_in[8];
    const float* Ws  = (const float*)d_in[9];
    const float* bs  = (const float*)d_in[10];
    const int* eidx  = (const int*)d_in[11];
    float* out = (float*)d_out;

    cudaFuncSetAttribute(proj_kernel, cudaFuncAttributeMaxDynamicSharedMemorySize, PROJ_SMEM);
    float* feat = nullptr;
    cudaGetSymbolAddress((void**)&feat, g_feat);

    const int nproj = (NN + BN - 1) / BN;

    for (int l = 0; l < 4; ++l) {
        const float* hin = (l == 0) ? x : feat;
        size_t off2 = (size_t)l * DH * DH;
        size_t offb = (size_t)l * DH;
        size_t offe = (size_t)l * DH * DE;

        initms_kernel<<<(NN * NH + 255) / 256, 256>>>();
        proj_kernel<<<nproj, PROJ_THREADS, PROJ_SMEM>>>(hin,
            Wq + off2, bq + offb, Wk + off2, bk + offb,
            Wv + off2, bv + offb, Ws + off2, bs + offb);
        eproj_kernel<<<EE / EPB, 256>>>(We + offe, ef);
        edgeA_kernel<<<(EE * NH) / 256, 256>>>(eidx);
        edgeB_kernel<<<(EE * NH) / 256, 256>>>(eidx);
        edgeC_kernel<<<(EE * NH) / 256, 256>>>(eidx,
            out + (size_t)NN * DH + (size_t)l * EE * NH);
        finish_kernel<<<(NN * DH + 255) / 256, 256>>>((l == 3) ? out : feat, (l < 3) ? 1 : 0);
    }
}

// round 7
// speedup vs baseline: 2.8317x; 1.4424x over previous
#include <cuda_runtime.h>
#include <math.h>
#include <float.h>

#define NN 50000
#define EE 400000
#define DH 128
#define DE 32
#define NH 8
#define CH 16

typedef unsigned long long ull;

// ---------------- scratch (device globals: no allocation allowed) ----------------
__device__ float g_q[(size_t)NN * DH];
__device__ float g_k[(size_t)NN * DH];
__device__ float g_v[(size_t)NN * DH];
__device__ float g_agg[(size_t)NN * DH];
__device__ float g_feat[(size_t)NN * DH];
__device__ float g_e[(size_t)EE * DH];          // materialized edge projection
__device__ float g_raw[(size_t)EE * NH];        // raw attention logits
// CSR (built once per call)
__device__ int g_deg[NN];
__device__ int g_fill[NN];
__device__ int g_rowptr[NN + 1];
__device__ int g_eperm[EE];

// ---------------- packed f32x2 helpers (2x fp32 FMA rate on sm_103a) -------------
__device__ __forceinline__ ull pk2(float lo, float hi) {
    ull r; asm("mov.b64 %0, {%1, %2};" : "=l"(r) : "f"(lo), "f"(hi)); return r;
}
__device__ __forceinline__ float2 upk2(ull a) {
    float2 r; asm("mov.b64 {%0, %1}, %2;" : "=f"(r.x), "=f"(r.y) : "l"(a)); return r;
}
__device__ __forceinline__ ull ffma2(ull a, ull b, ull c) {
    ull d; asm("fma.rn.f32x2 %0, %1, %2, %3;" : "=l"(d) : "l"(a), "l"(b), "l"(c)); return d;
}
__device__ __forceinline__ ull fadd2(ull a, ull b) {
    ull d; asm("add.rn.f32x2 %0, %1, %2;" : "=l"(d) : "l"(a), "l"(b)); return d;
}

// ---------------- fused 4-way node projection GEMM (unchanged, known-good) -------
#define BN 64
#define WPAD 132
#define PROJ_THREADS 256
#define PROJ_SMEM ((BN * DH + DH * WPAD) * 4)

__global__ void proj_kernel(const float* __restrict__ hin,
                            const float* __restrict__ Wq, const float* __restrict__ bq,
                            const float* __restrict__ Wk, const float* __restrict__ bk,
                            const float* __restrict__ Wv, const float* __restrict__ bv,
                            const float* __restrict__ Ws, const float* __restrict__ bs) {
    extern __shared__ float sh[];
    float* xs  = sh;             // [BN][DH]
    float* wsT = sh + BN * DH;   // [DH][WPAD]
    const int tid = threadIdx.x;
    const int node0 = blockIdx.x * BN;

    for (int i = tid; i < BN * DH / 4; i += PROJ_THREADS) {
        int n  = i / (DH / 4);
        int c4 = (i % (DH / 4)) * 4;
        float4 v = make_float4(0.f, 0.f, 0.f, 0.f);
        if (node0 + n < NN) v = *(const float4*)(hin + (size_t)(node0 + n) * DH + c4);
        *(float4*)(xs + n * DH + c4) = v;
    }

    const int cgrp = tid & 31;
    const int ngrp = tid >> 5;
    const int c0 = cgrp * 4;

    const float* Wlist[4] = {Wq, Wk, Wv, Ws};
    const float* Blist[4] = {bq, bk, bv, bs};
    float* Olist[4] = {g_q, g_k, g_v, g_agg};

    for (int w = 0; w < 4; ++w) {
        __syncthreads();
        const float* W = Wlist[w];
        for (int t = tid; t < DH * DH; t += PROJ_THREADS) {
            int ch = t >> 7, kk = t & (DH - 1);
            wsT[kk * WPAD + ch] = W[t];
        }
        __syncthreads();

        ull acc0[8], acc1[8];
#pragma unroll
        for (int i = 0; i < 8; ++i) { acc0[i] = 0ULL; acc1[i] = 0ULL; }

        const float* xrow = xs + (ngrp * 8) * DH;
#pragma unroll 8
        for (int kk = 0; kk < DH; ++kk) {
            ulonglong2 wp = *(const ulonglong2*)(wsT + kk * WPAD + c0);
#pragma unroll
            for (int i = 0; i < 8; ++i) {
                float xv = xrow[i * DH + kk];
                ull xx = pk2(xv, xv);
                acc0[i] = ffma2(xx, wp.x, acc0[i]);
                acc1[i] = ffma2(xx, wp.y, acc1[i]);
            }
        }

        float4 bias = *(const float4*)(Blist[w] + c0);
        float* O = Olist[w];
#pragma unroll
        for (int i = 0; i < 8; ++i) {
            int n = node0 + ngrp * 8 + i;
            if (n < NN) {
                float2 a = upk2(acc0[i]), b = upk2(acc1[i]);
                float4 o = make_float4(a.x + bias.x, a.y + bias.y, b.x + bias.z, b.y + bias.w);
                *(float4*)(O + (size_t)n * DH + c0) = o;
            }
        }
    }
}

// ---------------- edge projection GEMM: g_e = ef @ We^T  [E,32]x[32,128] ----------
#define EPB 64
__global__ void eproj_kernel(const float* __restrict__ We, const float* __restrict__ ef) {
    __shared__ float ws[DE][WPAD];
    __shared__ float efs[EPB][DE + 1];
    const int tid = threadIdx.x;
    const int e0 = blockIdx.x * EPB;

    for (int t = tid; t < DH * DE; t += 256) {
        int ch = t >> 5, k = t & (DE - 1);
        ws[k][ch] = We[t];
    }
    for (int t = tid; t < EPB * DE; t += 256) {
        efs[t >> 5][t & (DE - 1)] = ef[(size_t)e0 * DE + t];
    }
    __syncthreads();

    const int egrp = tid >> 5;
    const int cg = tid & 31;
    const int c0 = cg * 4;

    ull acc0[8], acc1[8];
#pragma unroll
    for (int i = 0; i < 8; ++i) { acc0[i] = 0ULL; acc1[i] = 0ULL; }

#pragma unroll
    for (int k = 0; k < DE; ++k) {
        ulonglong2 wp = *(const ulonglong2*)(&ws[k][c0]);
#pragma unroll
        for (int i = 0; i < 8; ++i) {
            float xv = efs[egrp * 8 + i][k];
            ull xx = pk2(xv, xv);
            acc0[i] = ffma2(xx, wp.x, acc0[i]);
            acc1[i] = ffma2(xx, wp.y, acc1[i]);
        }
    }

#pragma unroll
    for (int i = 0; i < 8; ++i) {
        int e = e0 + egrp * 8 + i;
        float2 a = upk2(acc0[i]), b = upk2(acc1[i]);
        *(float4*)(g_e + (size_t)e * DH + c0) = make_float4(a.x, a.y, b.x, b.y);
    }
}

// ---------------- CSR build (once per call) ---------------------------------------
__global__ void csr_zero_kernel() {
    int i = blockIdx.x * blockDim.x + threadIdx.x;
    if (i < NN) { g_deg[i] = 0; g_fill[i] = 0; }
}
__global__ void csr_hist_kernel(const int* __restrict__ eidx) {
    int i = blockIdx.x * blockDim.x + threadIdx.x;
    if (i < EE) atomicAdd(&g_deg[eidx[EE + i]], 1);
}
__global__ void csr_scan_kernel() {
    __shared__ int sh[1024];
    __shared__ int carry;
    const int tid = threadIdx.x;
    if (tid == 0) carry = 0;
    __syncthreads();
    for (int base = 0; base < NN; base += 1024) {
        int v = (base + tid < NN) ? g_deg[base + tid] : 0;
        sh[tid] = v;
        __syncthreads();
        for (int off = 1; off < 1024; off <<= 1) {
            int t = (tid >= off) ? sh[tid - off] : 0;
            __syncthreads();
            sh[tid] += t;
            __syncthreads();
        }
        if (base + tid < NN) g_rowptr[base + tid] = carry + sh[tid] - v;
        __syncthreads();
        if (tid == 0) carry += sh[1023];
        __syncthreads();
    }
    if (tid == 0) g_rowptr[NN] = carry;   // == EE
}
__global__ void csr_scatter_kernel(const int* __restrict__ eidx) {
    int i = blockIdx.x * blockDim.x + threadIdx.x;
    if (i >= EE) return;
    int dst = eidx[EE + i];
    int pos = g_rowptr[dst] + atomicAdd(&g_fill[dst], 1);
    g_eperm[pos] = i;
}

// ---------------- pass A: raw alpha (pure gather, no atomics) ---------------------
__global__ void edgeA_kernel(const int* __restrict__ eidx) {
    int gt = blockIdx.x * 256 + threadIdx.x;
    if (gt >= EE * NH) return;
    int e = gt >> 3, hh = gt & 7;
    int src = eidx[e], dst = eidx[EE + e];

    const ulonglong2* qp = (const ulonglong2*)(g_q + (size_t)dst * DH + hh * CH);
    const ulonglong2* kp = (const ulonglong2*)(g_k + (size_t)src * DH + hh * CH);
    const ulonglong2* ep = (const ulonglong2*)(g_e + (size_t)e   * DH + hh * CH);

    ull acc = 0ULL;
#pragma unroll
    for (int j = 0; j < 4; ++j) {
        ulonglong2 q2 = qp[j], k2 = kp[j], e2 = ep[j];
        acc = ffma2(q2.x, fadd2(k2.x, e2.x), acc);
        acc = ffma2(q2.y, fadd2(k2.y, e2.y), acc);
    }
    float2 r = upk2(acc);
    g_raw[gt] = (r.x + r.y) * 0.25f;   // / sqrt(C=16)
}

// ---------------- fused segment softmax + aggregate (warp per destination) --------
// Pass 1 lanes: h = lane&7, slot = lane>>3 — loop is UNIFORM in i0 (shfl legality)
// Pass 2 lanes: h2 = lane>>2, q = lane&3  — coalesced 512B row gathers, reg accum
__global__ void edgeC_kernel(const int* __restrict__ eidx, float* __restrict__ alpha_out) {
    const int gw = (blockIdx.x * 256 + threadIdx.x) >> 5;
    const int lane = threadIdx.x & 31;
    if (gw >= NN) return;
    const int d = gw;
    const int p0 = g_rowptr[d];
    const int deg = g_rowptr[d + 1] - p0;
    if (deg == 0) return;

    // warp-preload up to 32 edge ids + src ids
    int eL = -1, srcL = -1;
    if (lane < deg) { eL = g_eperm[p0 + lane]; srcL = eidx[eL]; }

    // ---- pass 1: online softmax stats (uniform trip count, shfl by all lanes) ----
    const int h = lane & 7, slot = lane >> 3;
    float m = -FLT_MAX, s = 0.f;
    for (int i0 = 0; i0 < deg; i0 += 4) {
        int i = i0 + slot;                 // may be >= deg for trailing lanes
        int ic = min(i, deg - 1);          // clamped: safe fetch index
        int e;
        if (i0 < 32) {                     // uniform predicate (i0 mult of 4, slot<4 => i<=31)
            e = __shfl_sync(0xffffffffu, eL, ic);
        } else {                           // here deg-1 >= i0 >= 32, so p0+ic < p0+deg <= EE
            e = g_eperm[p0 + ic];
        }
        if (i < deg) {
            float r = g_raw[(size_t)e * NH + h];
            float nm = fmaxf(m, r);
            s = s * __expf(m - nm) + __expf(r - nm);
            m = nm;
        }
    }
#pragma unroll
    for (int off = 8; off < 32; off <<= 1) {
        float mo = __shfl_xor_sync(0xffffffffu, m, off);
        float so = __shfl_xor_sync(0xffffffffu, s, off);
        float nm = fmaxf(m, mo);
        s = s * __expf(m - nm) + so * __expf(mo - nm);
        m = nm;
    }

    // redistribute stats to pass-2 lane layout
    const int h2 = lane >> 2, q = lane & 3;
    float mh = __shfl_sync(0xffffffffu, m, h2);
    float sh = __shfl_sync(0xffffffffu, s, h2);
    float inv = 1.f / (sh + 1e-16f);

    // ---- pass 2: accumulate (v+e)*alpha (trip count uniform across warp) ----
    float4 acc = make_float4(0.f, 0.f, 0.f, 0.f);
    for (int i = 0; i < deg; ++i) {
        int e, src;
        if (i < 32) {
            e = __shfl_sync(0xffffffffu, eL, i);
            src = __shfl_sync(0xffffffffu, srcL, i);
        } else {
            e = g_eperm[p0 + i];
            src = eidx[e];
        }
        float r = g_raw[(size_t)e * NH + h2];
        float a = __expf(r - mh) * inv;
        float4 v4 = *(const float4*)(g_v + (size_t)src * DH + lane * 4);
        float4 e4 = *(const float4*)(g_e + (size_t)e   * DH + lane * 4);
        acc.x += (v4.x + e4.x) * a;
        acc.y += (v4.y + e4.y) * a;
        acc.z += (v4.z + e4.z) * a;
        acc.w += (v4.w + e4.w) * a;
        if (q == 0) alpha_out[(size_t)e * NH + h2] = a;
    }

    float4 skip = *(const float4*)(g_agg + (size_t)d * DH + lane * 4);
    acc.x += skip.x; acc.y += skip.y; acc.z += skip.z; acc.w += skip.w;
    *(float4*)(g_agg + (size_t)d * DH + lane * 4) = acc;
}

// ---------------- epilogue: exact-erf GELU + feature handoff ----------------------
__global__ void finish_kernel(float* __restrict__ dst, int apply_gelu) {
    int i = blockIdx.x * blockDim.x + threadIdx.x;
    if (i >= NN * DH) return;
    float x = g_agg[i];
    if (apply_gelu) x = x * normcdff(x);   // 0.5*x*(1+erf(x/sqrt(2)))
    dst[i] = x;
}

// ---------------- launch ----------------------------------------------------------
extern "C" void kernel_launch(void* const* d_in, const int* in_sizes, int n_in,
                              void* d_out, int out_size) {
    const float* x   = (const float*)d_in[0];
    const float* ef  = (const float*)d_in[1];
    const float* Wq  = (const float*)d_in[2];
    const float* bq  = (const float*)d_in[3];
    const float* Wk  = (const float*)d_in[4];
    const float* bk  = (const float*)d_in[5];
    const float* Wv  = (const float*)d_in[6];
    const float* bv  = (const float*)d_in[7];
    const float* We  = (const float*)d_in[8];
    const float* Ws  = (const float*)d_in[9];
    const float* bs  = (const float*)d_in[10];
    const int* eidx  = (const int*)d_in[11];
    float* out = (float*)d_out;

    cudaFuncSetAttribute(proj_kernel, cudaFuncAttributeMaxDynamicSharedMemorySize, PROJ_SMEM);
    float* feat = nullptr;
    cudaGetSymbolAddress((void**)&feat, g_feat);

    const int nproj = (NN + BN - 1) / BN;

    // CSR build: once per call, reused by all 4 layers
    csr_zero_kernel<<<(NN + 255) / 256, 256>>>();
    csr_hist_kernel<<<(EE + 255) / 256, 256>>>(eidx);
    csr_scan_kernel<<<1, 1024>>>();
    csr_scatter_kernel<<<(EE + 255) / 256, 256>>>(eidx);

    for (int l = 0; l < 4; ++l) {
        const float* hin = (l == 0) ? x : feat;
        size_t off2 = (size_t)l * DH * DH;
        size_t offb = (size_t)l * DH;
        size_t offe = (size_t)l * DH * DE;

        proj_kernel<<<nproj, PROJ_THREADS, PROJ_SMEM>>>(hin,
            Wq + off2, bq + offb, Wk + off2, bk + offb,
            Wv + off2, bv + offb, Ws + off2, bs + offb);
        eproj_kernel<<<EE / EPB, 256>>>(We + offe, ef);
        edgeA_kernel<<<(EE * NH) / 256, 256>>>(eidx);
        edgeC_kernel<<<(NN * 32 + 255) / 256, 256>>>(eidx,
            out + (size_t)NN * DH + (size_t)l * EE * NH);
        finish_kernel<<<(NN * DH + 255) / 256, 256>>>((l == 3) ? out : feat, (l < 3) ? 1 : 0);
    }
}